// round 9
// baseline (speedup 1.0000x reference)
#include <cuda_runtime.h>

#define TN (1 << 20)
#define LOG2TN 20
#define KM 3
#define C_ALPHA 2000.0f
#define C_TAU 1e-7f
#define C_TAU2 1e-14f
#define PI_D 3.14159265358979323846

typedef unsigned long long ull;

// ---------------- scratch (device globals; no allocation allowed) ----------------
__device__ float2 g_A[3 * TN];        // FFT ping buffer
__device__ float2 g_Bb[3 * TN];       // FFT pong buffer (fhat after fwd)
__device__ float2 g_lamPrev[TN];      // lambda stash / final lambda
struct __align__(128) Acc2Blk { double a[2][8]; };
__device__ Acc2Blk g_acc2;            // parity-split per-iteration accumulators
struct __align__(128) CtrBlk { unsigned c; unsigned pad[31]; };
__device__ CtrBlk g_ctrB;             // arrival counter (own line)
struct __align__(128) RelBlk {        // release line: go + done + omega, one 128B line
    volatile unsigned go;
    volatile unsigned done;
    volatile float o0, o1, o2;
    unsigned pad[27];
};
__device__ RelBlk g_rel;
__device__ float g_om[KM];

__device__ __forceinline__ float frcp(float x) {
    float r; asm("rcp.approx.f32 %0, %1;" : "=f"(r) : "f"(x)); return r;
}

// ---------------- packed f32x2 helpers ----------------
__device__ __forceinline__ ull pk(float lo, float hi) {
    ull r; asm("mov.b64 %0, {%1, %2};" : "=l"(r) : "f"(lo), "f"(hi)); return r;
}
__device__ __forceinline__ void upk(float& lo, float& hi, ull v) {
    asm("mov.b64 {%0, %1}, %2;" : "=f"(lo), "=f"(hi) : "l"(v));
}
__device__ __forceinline__ ull fma2(ull a, ull b, ull c) {
    ull d; asm("fma.rn.f32x2 %0, %1, %2, %3;" : "=l"(d) : "l"(a), "l"(b), "l"(c)); return d;
}
__device__ __forceinline__ ull add2(ull a, ull b) {
    ull d; asm("add.rn.f32x2 %0, %1, %2;" : "=l"(d) : "l"(a), "l"(b)); return d;
}
__device__ __forceinline__ ull mul2(ull a, ull b) {
    ull d; asm("mul.rn.f32x2 %0, %1, %2;" : "=l"(d) : "l"(a), "l"(b)); return d;
}
__device__ __forceinline__ ull rcp2(ull a) {
    float lo, hi; upk(lo, hi, a); return pk(frcp(lo), frcp(hi));
}

// ---------------- complex helpers ----------------
__device__ __forceinline__ float2 cadd(float2 a, float2 b) { return make_float2(a.x + b.x, a.y + b.y); }
__device__ __forceinline__ float2 csub(float2 a, float2 b) { return make_float2(a.x - b.x, a.y - b.y); }
__device__ __forceinline__ float2 cmul(float2 a, float2 b) {
    return make_float2(a.x * b.x - a.y * b.y, a.x * b.y + a.y * b.x);
}

// ---------------- radix-16 butterfly ----------------
template <bool FWD>
__device__ __forceinline__ void bf4(float2 a, float2 b, float2 c, float2 d,
                                    float2& o0, float2& o1, float2& o2, float2& o3) {
    float2 apc = cadd(a, c), amc = csub(a, c);
    float2 bpd = cadd(b, d), bmd = csub(b, d);
    o0 = cadd(apc, bpd);
    o2 = csub(apc, bpd);
    if (FWD) {
        o1 = make_float2(amc.x + bmd.y, amc.y - bmd.x);
        o3 = make_float2(amc.x - bmd.y, amc.y + bmd.x);
    } else {
        o1 = make_float2(amc.x - bmd.y, amc.y + bmd.x);
        o3 = make_float2(amc.x + bmd.y, amc.y - bmd.x);
    }
}

template <bool FWD>
__device__ __forceinline__ void fft16(float2* z) {
    const float S  = FWD ? -1.f : 1.f;
    const float C1 = 0.92387953251128674f;
    const float S1 = 0.38268343236508977f;
    const float R  = 0.70710678118654752f;
    float2 A[16];
#pragma unroll
    for (int n1 = 0; n1 < 4; n1++)
        bf4<FWD>(z[n1], z[n1 + 4], z[n1 + 8], z[n1 + 12],
                 A[n1 * 4 + 0], A[n1 * 4 + 1], A[n1 * 4 + 2], A[n1 * 4 + 3]);
    A[5]  = cmul(A[5],  make_float2( C1,  S * S1));
    A[6]  = cmul(A[6],  make_float2( R,   S * R ));
    A[7]  = cmul(A[7],  make_float2( S1,  S * C1));
    A[9]  = cmul(A[9],  make_float2( R,   S * R ));
    A[10] = make_float2(-S * A[10].y, S * A[10].x);
    A[11] = cmul(A[11], make_float2(-R,   S * R ));
    A[13] = cmul(A[13], make_float2( S1,  S * C1));
    A[14] = cmul(A[14], make_float2(-R,   S * R ));
    A[15] = cmul(A[15], make_float2(-C1, -S * S1));
#pragma unroll
    for (int k2 = 0; k2 < 4; k2++)
        bf4<FWD>(A[k2], A[4 + k2], A[8 + k2], A[12 + k2],
                 z[k2], z[k2 + 4], z[k2 + 8], z[k2 + 12]);
}

// ---------------- forward stage 0 fused with (-1)^n pack AND global init ----------------
__global__ void __launch_bounds__(256) fwd0_kernel(const float* __restrict__ x,
                                                   const float* __restrict__ om0in) {
    if (blockIdx.x == 0 && threadIdx.x == 0) {
        g_om[0] = 0.5f * om0in[0]; g_om[1] = 0.5f * om0in[1]; g_om[2] = 0.5f * om0in[2];
#pragma unroll
        for (int i = 0; i < 16; i++) ((double*)g_acc2.a)[i] = 0.0;
        g_ctrB.c = 0u;
        g_rel.go = 0u; g_rel.done = 0u;
    }
    int p = blockIdx.x * blockDim.x + threadIdx.x;
    float sgn = (p & 1) ? -1.f : 1.f;
    float2 z[16];
#pragma unroll
    for (int j = 0; j < 16; j++) z[j] = make_float2(sgn * x[p + j * 65536], 0.f);
    fft16<true>(z);
    float th0 = (float)(-2.0 * PI_D / (double)TN);
    float sn, cs;
    sincosf(th0 * (float)p, &sn, &cs);
    float2 w = make_float2(cs, sn), cur = w;
    int ob = p << 4;
    g_Bb[ob] = z[0];
#pragma unroll
    for (int r = 1; r < 16; r++) {
        g_Bb[ob + r] = cmul(z[r], cur);
        cur = cmul(cur, w);
    }
}

// ---------------- generic radix-16 Stockham stage (batched) ----------------
template <bool FWD>
__global__ void __launch_bounds__(256) fft16_stage(int inIsB, int log2s, float th0) {
    int gid  = blockIdx.x * blockDim.x + threadIdx.x;
    int tid  = gid & 65535;
    int base = (gid >> 16) << LOG2TN;
    const float2* __restrict__ X = (inIsB ? g_Bb : g_A) + base;
    float2* __restrict__       Y = (inIsB ? g_A : g_Bb) + base;
    int s_ = 1 << log2s;
    int q  = tid & (s_ - 1);
    int p  = tid >> log2s;
    int m  = TN >> (log2s + 4);

    float2 z[16];
#pragma unroll
    for (int j = 0; j < 16; j++) z[j] = X[q + ((p + j * m) << log2s)];
    fft16<FWD>(z);
    float sn, cs;
    sincosf(th0 * (float)p, &sn, &cs);
    float2 w = make_float2(cs, sn), cur = w;
    int ob = q + ((p << 4) << log2s);
    Y[ob] = z[0];
#pragma unroll
    for (int r = 1; r < 16; r++) {
        Y[ob + (r << log2s)] = cmul(z[r], cur);
        cur = cmul(cur, w);
    }
}

// ---------------- u reconstruction + inverse stage 0 (fused, standalone) ----------------
__global__ void __launch_bounds__(256) ustage0_kernel() {
    int gid = blockIdx.x * blockDim.x + threadIdx.x;   // 0..65535
    float om0 = g_om[0], om1 = g_om[1], om2 = g_om[2];
    const float FRC = 1.0f / 1048576.0f;
    float frBase = fmaf((float)gid, FRC, -0.5f);

    float nrA[16], niA[16];
#pragma unroll
    for (int e = 0; e < 16; e++) {
        int t = e * 65536 + gid;
        float2 fh = g_Bb[t];
        float2 la = g_lamPrev[t];
        float fr = frBase + (float)e * 0.0625f;
        float d0 = fr - om0; d0 *= d0;
        float d1 = fr - om1; d1 *= d1;
        float d2 = fr - om2; d2 *= d2;
        float g0 = frcp(fmaf(C_ALPHA, (d0 + C_TAU2) + d1, 1.0f));
        float g1 = frcp(fmaf(C_ALPHA, ((d1 + C_TAU2) + d0) + d2, 1.0f));
        float g2 = frcp(fmaf(C_ALPHA, (d2 + C_TAU2) + d1, 1.0f));
        float G  = (g0 + g1) + g2;
        float inv = frcp(1.0f - 0.5f * C_TAU * G);
        float lox = (la.x - C_TAU * fh.x * (G - 1.0f)) * inv;
        float loy = (la.y - C_TAU * fh.y * (G - 1.0f)) * inv;
        nrA[e] = fmaf(-0.5f, lox, fh.x);
        niA[e] = fmaf(-0.5f, loy, fh.y);
    }

    float th0 = (float)(2.0 * PI_D / (double)TN);
    float sn, cs;
    sincosf(th0 * (float)gid, &sn, &cs);
    float2 w = make_float2(cs, sn);
    int ob = gid << 4;

#pragma unroll
    for (int k = 0; k < 3; k++) {
        float2 z[16];
#pragma unroll
        for (int e = 0; e < 16; e++) {
            float fr = frBase + (float)e * 0.0625f;
            float d0 = fr - om0; d0 *= d0;
            float d1 = fr - om1; d1 *= d1;
            float d2 = fr - om2; d2 *= d2;
            float gk;
            if (k == 0)      gk = frcp(fmaf(C_ALPHA, (d0 + C_TAU2) + d1, 1.0f));
            else if (k == 1) gk = frcp(fmaf(C_ALPHA, ((d1 + C_TAU2) + d0) + d2, 1.0f));
            else             gk = frcp(fmaf(C_ALPHA, (d2 + C_TAU2) + d1, 1.0f));
            z[e] = make_float2(nrA[e] * gk, niA[e] * gk);
        }
        fft16<false>(z);
        float2* __restrict__ Y = g_A + (k << LOG2TN);
        float2 cur = w;
        Y[ob] = z[0];
#pragma unroll
        for (int r = 1; r < 16; r++) {
            Y[ob + r] = cmul(z[r], cur);
            cur = cmul(cur, w);
        }
    }
}

// ---------------- final inverse stage fused with real output (reads g_Bb) ----------------
__global__ void __launch_bounds__(256) inv_final_kernel(float* __restrict__ out) {
    int gid = blockIdx.x * blockDim.x + threadIdx.x;
    int q = gid & 65535;
    int b = gid >> 16;
    const float2* __restrict__ X = g_Bb + (b << LOG2TN);
    float2 z[16];
#pragma unroll
    for (int j = 0; j < 16; j++) z[j] = X[q + (j << 16)];
    fft16<false>(z);
    float sg = (q & 1) ? -(1.0f / 1048576.0f) : (1.0f / 1048576.0f);
    float* __restrict__ o = out + (b << LOG2TN);
#pragma unroll
    for (int r = 0; r < 16; r++) o[q + (r << 16)] = z[r].x * sg;
}

// ---------------- persistent VMD iteration kernel (packed f32x2) ----------------
#define NBP 128
#define NTP 512
#define PJ 8      // 8 pairs = 16 elements per thread; NBP*NTP*16 = 2^20

__global__ void __launch_bounds__(NTP) vmd_persist() {
    int tid = threadIdx.x;
    int gid = blockIdx.x * NTP + tid;

    ull fhxP[PJ], fhyP[PJ], laxP[PJ], layP[PJ];
#pragma unroll
    for (int j = 0; j < PJ; j++) {
        float2 v0 = g_Bb[(2 * j) * 65536 + gid];
        float2 v1 = g_Bb[(2 * j + 1) * 65536 + gid];
        fhxP[j] = pk(v0.x, v1.x);
        fhyP[j] = pk(v0.y, v1.y);
        laxP[j] = 0ULL; layP[j] = 0ULL;
    }
    float om0 = g_om[0], om1 = g_om[1], om2 = g_om[2];
    float oD0 = om0, oD1 = om1, oD2 = om2;

    __shared__ float sred[8][NTP / 32];
    __shared__ float sOm[3];
    __shared__ int   sTerm;

    const float FRC = 1.0f / 1048576.0f;
    float frBase = fmaf((float)gid, FRC, -0.5f);

    const ull T2P   = pk(C_TAU2, C_TAU2);
    const ull ONEP  = pk(1.0f, 1.0f);
    const ull ALP   = pk(C_ALPHA, C_ALPHA);
    const ull NHALF = pk(-0.5f, -0.5f);
    const ull TAUP  = pk(C_TAU, C_TAU);
    const ull NTAUP = pk(-C_TAU, -C_TAU);
    const ull C1P   = pk(1.0f - 0.5f * C_TAU, 1.0f - 0.5f * C_TAU);

    for (int n = 0; n < 50; n++) {
        ull a0 = 0ULL, a1 = 0ULL, a2 = 0ULL, a3 = 0ULL, a4 = 0ULL, a5 = 0ULL;
        float a6 = 0.f, a7 = 0.f;
        bool doDiff  = (n > 0) && (n % 10 == 0);
        bool doStash = (n % 10 == 9) && (n < 49);

        ull NOM0 = pk(-om0, -om0), NOM1 = pk(-om1, -om1), NOM2 = pk(-om2, -om2);

#pragma unroll
        for (int j = 0; j < PJ; j++) {
            float fr0 = frBase + (float)(2 * j) * 0.0625f;
            float fr1 = fr0 + 0.0625f;
            ull frP = pk(fr0, fr1);

            ull t0 = add2(frP, NOM0); ull d0 = mul2(t0, t0);
            ull t1 = add2(frP, NOM1); ull d1 = mul2(t1, t1);
            ull t2 = add2(frP, NOM2); ull d2 = mul2(t2, t2);
            ull e0 = add2(add2(d0, d1), T2P);
            ull e1 = add2(e0, d2);
            ull e2 = add2(add2(d1, d2), T2P);
            ull g0 = rcp2(fma2(ALP, e0, ONEP));
            ull g1 = rcp2(fma2(ALP, e1, ONEP));
            ull g2 = rcp2(fma2(ALP, e2, ONEP));

            ull nr = fma2(NHALF, laxP[j], fhxP[j]);
            ull ni = fma2(NHALF, layP[j], fhyP[j]);
            ull m2 = fma2(ni, ni, mul2(nr, nr));

            ull p0 = mul2(m2, mul2(g0, g0));
            ull p1 = mul2(m2, mul2(g1, g1));
            ull p2 = mul2(m2, mul2(g2, g2));
            a0 = add2(a0, p0); a1 = add2(a1, p1); a2 = add2(a2, p2);
            a3 = fma2(p0, frP, a3); a4 = fma2(p1, frP, a4); a5 = fma2(p2, frP, a5);

            if (doDiff) {
                float nrl, nrh, nil, nih, g0l, g0h, g1l, g1h, g2l, g2h;
                upk(nrl, nrh, nr); upk(nil, nih, ni);
                upk(g0l, g0h, g0); upk(g1l, g1h, g1); upk(g2l, g2h, g2);
                float fhxl, fhxh, fhyl, fhyh;
                upk(fhxl, fhxh, fhxP[j]); upk(fhyl, fhyh, fhyP[j]);
#pragma unroll
                for (int s = 0; s < 2; s++) {
                    float fr  = s ? fr1 : fr0;
                    float cnr = s ? nrh : nrl, cni = s ? nih : nil;
                    float cg0 = s ? g0h : g0l, cg1 = s ? g1h : g1l, cg2 = s ? g2h : g2l;
                    float cfx = s ? fhxh : fhxl, cfy = s ? fhyh : fhyl;
                    float2 lp = g_lamPrev[(2 * j + s) * 65536 + gid];
                    float q0 = fr - oD0; q0 *= q0;
                    float q1 = fr - oD1; q1 *= q1;
                    float q2 = fr - oD2; q2 *= q2;
                    float h0 = frcp(fmaf(C_ALPHA, (q0 + C_TAU2) + q1, 1.0f));
                    float h1 = frcp(fmaf(C_ALPHA, ((q1 + C_TAU2) + q0) + q2, 1.0f));
                    float h2 = frcp(fmaf(C_ALPHA, (q2 + C_TAU2) + q1, 1.0f));
                    float mr = fmaf(-0.5f, lp.x, cfx);
                    float mi = fmaf(-0.5f, lp.y, cfy);
                    float ex0 = cnr * cg0 - mr * h0, ey0 = cni * cg0 - mi * h0;
                    float ex1 = cnr * cg1 - mr * h1, ey1 = cni * cg1 - mi * h1;
                    float ex2 = cnr * cg2 - mr * h2, ey2 = cni * cg2 - mi * h2;
                    a6 += ex0 * ex0 + ey0 * ey0 + ex1 * ex1 + ey1 * ey1 + ex2 * ex2 + ey2 * ey2;
                    a7 += (mr * mr + mi * mi) * (h0 * h0 + h1 * h1 + h2 * h2);
                }
            }
            if (doStash) {
                float lxl, lxh, lyl, lyh;
                upk(lxl, lxh, laxP[j]); upk(lyl, lyh, layP[j]);
                g_lamPrev[(2 * j) * 65536 + gid]     = make_float2(lxl, lyl);
                g_lamPrev[(2 * j + 1) * 65536 + gid] = make_float2(lxh, lyh);
            }

            ull G   = add2(add2(g0, g1), g2);
            ull tG1 = fma2(TAUP, G, NTAUP);          // tau*(G-1)
            laxP[j] = fma2(nr, tG1, mul2(laxP[j], C1P));
            layP[j] = fma2(ni, tG1, mul2(layP[j], C1P));
        }

        // ---- unpack packed accumulators, block reduce 8 scalars ----
        float vals[8];
        {
            float lo, hi;
            upk(lo, hi, a0); vals[0] = lo + hi;
            upk(lo, hi, a1); vals[1] = lo + hi;
            upk(lo, hi, a2); vals[2] = lo + hi;
            upk(lo, hi, a3); vals[3] = lo + hi;
            upk(lo, hi, a4); vals[4] = lo + hi;
            upk(lo, hi, a5); vals[5] = lo + hi;
            vals[6] = a6; vals[7] = a7;
        }
#pragma unroll
        for (int i = 0; i < 8; i++) {
            float v = vals[i];
#pragma unroll
            for (int o = 16; o > 0; o >>= 1) v += __shfl_down_sync(0xffffffffu, v, o);
            vals[i] = v;
        }
        int wid = tid >> 5, lid = tid & 31;
        if (lid == 0) {
#pragma unroll
            for (int i = 0; i < 8; i++) sred[i][wid] = vals[i];
        }
        __syncthreads();
        if (tid < 8) {
            double s = 0.0;
#pragma unroll
            for (int w = 0; w < NTP / 32; w++) s += (double)sred[tid][w];
            atomicAdd(&g_acc2.a[n & 1][tid], s);
        }
        __syncthreads();

        // ---- arrival; last arriver computes omega once, publishes one line ----
        if (tid == 0) {
            __threadfence();   // release: block's accumulator atomics visible
            unsigned old = atomicAdd(&g_ctrB.c, 1u);
            if (old == (unsigned)NBP * (unsigned)(n + 1) - 1u) {
                __threadfence();
                volatile double* A = g_acc2.a[n & 1];
                double i0 = A[0], i1 = A[1], i2 = A[2], i3 = A[3];
                double i4 = A[4], i5 = A[5], i6 = A[6], i7 = A[7];
                float f0 = (float)i0, f1 = (float)i1, f2 = (float)i2;
                float on0 = (float)i3 * frcp(f0 + 1e-8f);
                float on1 = (float)i4 * frcp(f1 + 1e-8f);
                float on2 = (float)i5 * frcp(f2 + 1e-8f);
                float odiff = (fabsf(on0 - on2) + fabsf(on1 - on0) + fabsf(on2 - on1)) * (1.0f / 3.0f);
                float udiff = (n == 0) ? (f0 + f1 + f2) * 1e8f
                                       : (float)i6 * frcp((float)i7 + 1e-8f);
                int dn = (n % 10 == 0) && (udiff < 1e-6f) && (odiff < 1e-6f);
                g_rel.o0 = on0; g_rel.o1 = on1; g_rel.o2 = on2; g_rel.done = (unsigned)dn;
                __threadfence();
                g_rel.go = (unsigned)(n + 1);
                // off-critical-path: reset this parity for iteration n+2
                A[0] = 0.0; A[1] = 0.0; A[2] = 0.0; A[3] = 0.0;
                A[4] = 0.0; A[5] = 0.0; A[6] = 0.0; A[7] = 0.0;
                __threadfence();
            }
            while (g_rel.go < (unsigned)(n + 1)) { __nanosleep(32); }
            __threadfence();   // acquire
            sOm[0] = g_rel.o0; sOm[1] = g_rel.o1; sOm[2] = g_rel.o2;
            sTerm = (g_rel.done != 0u) || (n == 49);
        }
        __syncthreads();

        if (sTerm) {
            // terminal: store raw lambda_new; ustage0_kernel does inversion + u + inv stage 0
#pragma unroll
            for (int j = 0; j < PJ; j++) {
                float lxl, lxh, lyl, lyh;
                upk(lxl, lxh, laxP[j]); upk(lyl, lyh, layP[j]);
                g_lamPrev[(2 * j) * 65536 + gid]     = make_float2(lxl, lyl);
                g_lamPrev[(2 * j + 1) * 65536 + gid] = make_float2(lxh, lyh);
            }
            if (gid == 0) { g_om[0] = om0; g_om[1] = om1; g_om[2] = om2; }
            break;
        }
        oD0 = om0; oD1 = om1; oD2 = om2;
        om0 = sOm[0]; om1 = sOm[1]; om2 = sOm[2];
        __syncthreads();
    }
}

// ---------------- launch ----------------
extern "C" void kernel_launch(void* const* d_in, const int* in_sizes, int n_in,
                              void* d_out, int out_size) {
    const float* x   = (const float*)d_in[0];
    const float* om0 = (const float*)d_in[1];
    float* out = (float*)d_out;

    // forward FFT of (-1)^n x (stage 0 carries global init): launches #1..#5
    fwd0_kernel<<<256, 256>>>(x, om0);
    for (int i = 1; i < 5; i++) {
        float th0 = (float)(-2.0 * PI_D * (double)(1 << (4 * i)) / (double)TN);
        fft16_stage<true><<<256, 256>>>(i & 1, 4 * i, th0);
    }

    vmd_persist<<<NBP, NTP>>>();      // launch #6 (ncu -s 5 -c 1 captures this)

    ustage0_kernel<<<256, 256>>>();   // lambda -> u (3 batches) + inverse stage 0 -> g_A

    // inverse stages 1..3 (batch 3): A->B->A->B
    for (int i = 1; i < 4; i++) {
        float th0 = (float)(2.0 * PI_D * (double)(1 << (4 * i)) / (double)TN);
        fft16_stage<false><<<768, 256>>>(1 - (i & 1), 4 * i, th0);
    }
    // final stage fused with real output (reads g_Bb)
    inv_final_kernel<<<768, 256>>>(out);
}

// round 10
// speedup vs baseline: 1.0574x; 1.0574x over previous
#include <cuda_runtime.h>

#define TN (1 << 20)
#define LOG2TN 20
#define KM 3
#define C_ALPHA 2000.0f
#define C_TAU 1e-7f
#define C_TAU2 1e-14f
#define PI_D 3.14159265358979323846

typedef unsigned long long ull;

// ---------------- scratch (device globals; no allocation allowed) ----------------
__device__ float2 g_A[2 * TN];        // FFT ping buffer (2 batches now)
__device__ float2 g_Bb[2 * TN];       // FFT pong buffer; [0..TN) holds fhat after fwd
__device__ float2 g_lamPrev[TN];      // lambda stash / final lambda
struct __align__(128) AccBlk { double a[8]; double pad[8]; };
__device__ AccBlk g_accB;             // monotone accumulators (own line)
struct __align__(128) CtrBlk { unsigned c; unsigned pad[31]; };
__device__ CtrBlk g_ctrB;             // arrival counter (own line)
struct __align__(128) GoBlk { volatile unsigned g; unsigned pad[31]; };
__device__ GoBlk g_goB;               // release word (own line)
__device__ float g_om[KM];

__device__ __forceinline__ float frcp(float x) {
    float r; asm("rcp.approx.f32 %0, %1;" : "=f"(r) : "f"(x)); return r;
}

// ---------------- packed f32x2 helpers ----------------
__device__ __forceinline__ ull pk(float lo, float hi) {
    ull r; asm("mov.b64 %0, {%1, %2};" : "=l"(r) : "f"(lo), "f"(hi)); return r;
}
__device__ __forceinline__ void upk(float& lo, float& hi, ull v) {
    asm("mov.b64 {%0, %1}, %2;" : "=f"(lo), "=f"(hi) : "l"(v));
}
__device__ __forceinline__ ull fma2(ull a, ull b, ull c) {
    ull d; asm("fma.rn.f32x2 %0, %1, %2, %3;" : "=l"(d) : "l"(a), "l"(b), "l"(c)); return d;
}
__device__ __forceinline__ ull add2(ull a, ull b) {
    ull d; asm("add.rn.f32x2 %0, %1, %2;" : "=l"(d) : "l"(a), "l"(b)); return d;
}
__device__ __forceinline__ ull mul2(ull a, ull b) {
    ull d; asm("mul.rn.f32x2 %0, %1, %2;" : "=l"(d) : "l"(a), "l"(b)); return d;
}
__device__ __forceinline__ ull rcp2(ull a) {
    float lo, hi; upk(lo, hi, a); return pk(frcp(lo), frcp(hi));
}

// ---------------- complex helpers ----------------
__device__ __forceinline__ float2 cadd(float2 a, float2 b) { return make_float2(a.x + b.x, a.y + b.y); }
__device__ __forceinline__ float2 csub(float2 a, float2 b) { return make_float2(a.x - b.x, a.y - b.y); }
__device__ __forceinline__ float2 cmul(float2 a, float2 b) {
    return make_float2(a.x * b.x - a.y * b.y, a.x * b.y + a.y * b.x);
}

// ---------------- radix-16 butterfly ----------------
template <bool FWD>
__device__ __forceinline__ void bf4(float2 a, float2 b, float2 c, float2 d,
                                    float2& o0, float2& o1, float2& o2, float2& o3) {
    float2 apc = cadd(a, c), amc = csub(a, c);
    float2 bpd = cadd(b, d), bmd = csub(b, d);
    o0 = cadd(apc, bpd);
    o2 = csub(apc, bpd);
    if (FWD) {
        o1 = make_float2(amc.x + bmd.y, amc.y - bmd.x);
        o3 = make_float2(amc.x - bmd.y, amc.y + bmd.x);
    } else {
        o1 = make_float2(amc.x - bmd.y, amc.y + bmd.x);
        o3 = make_float2(amc.x + bmd.y, amc.y - bmd.x);
    }
}

template <bool FWD>
__device__ __forceinline__ void fft16(float2* z) {
    const float S  = FWD ? -1.f : 1.f;
    const float C1 = 0.92387953251128674f;
    const float S1 = 0.38268343236508977f;
    const float R  = 0.70710678118654752f;
    float2 A[16];
#pragma unroll
    for (int n1 = 0; n1 < 4; n1++)
        bf4<FWD>(z[n1], z[n1 + 4], z[n1 + 8], z[n1 + 12],
                 A[n1 * 4 + 0], A[n1 * 4 + 1], A[n1 * 4 + 2], A[n1 * 4 + 3]);
    A[5]  = cmul(A[5],  make_float2( C1,  S * S1));
    A[6]  = cmul(A[6],  make_float2( R,   S * R ));
    A[7]  = cmul(A[7],  make_float2( S1,  S * C1));
    A[9]  = cmul(A[9],  make_float2( R,   S * R ));
    A[10] = make_float2(-S * A[10].y, S * A[10].x);
    A[11] = cmul(A[11], make_float2(-R,   S * R ));
    A[13] = cmul(A[13], make_float2( S1,  S * C1));
    A[14] = cmul(A[14], make_float2(-R,   S * R ));
    A[15] = cmul(A[15], make_float2(-C1, -S * S1));
#pragma unroll
    for (int k2 = 0; k2 < 4; k2++)
        bf4<FWD>(A[k2], A[4 + k2], A[8 + k2], A[12 + k2],
                 z[k2], z[k2 + 4], z[k2 + 8], z[k2 + 12]);
}

// ---------------- forward stage 0 fused with (-1)^n pack AND global init ----------------
__global__ void __launch_bounds__(256) fwd0_kernel(const float* __restrict__ x,
                                                   const float* __restrict__ om0in) {
    if (blockIdx.x == 0 && threadIdx.x == 0) {
        g_om[0] = 0.5f * om0in[0]; g_om[1] = 0.5f * om0in[1]; g_om[2] = 0.5f * om0in[2];
#pragma unroll
        for (int i = 0; i < 8; i++) g_accB.a[i] = 0.0;
        g_ctrB.c = 0u;
        g_goB.g = 0u;
    }
    int p = blockIdx.x * blockDim.x + threadIdx.x;
    float sgn = (p & 1) ? -1.f : 1.f;
    float2 z[16];
#pragma unroll
    for (int j = 0; j < 16; j++) z[j] = make_float2(sgn * x[p + j * 65536], 0.f);
    fft16<true>(z);
    float th0 = (float)(-2.0 * PI_D / (double)TN);
    float sn, cs;
    sincosf(th0 * (float)p, &sn, &cs);
    float2 w = make_float2(cs, sn), cur = w;
    int ob = p << 4;
    g_Bb[ob] = z[0];
#pragma unroll
    for (int r = 1; r < 16; r++) {
        g_Bb[ob + r] = cmul(z[r], cur);
        cur = cmul(cur, w);
    }
}

// ---------------- generic radix-16 Stockham stage (batched) ----------------
template <bool FWD>
__global__ void __launch_bounds__(256) fft16_stage(int inIsB, int log2s, float th0) {
    int gid  = blockIdx.x * blockDim.x + threadIdx.x;
    int tid  = gid & 65535;
    int base = (gid >> 16) << LOG2TN;
    const float2* __restrict__ X = (inIsB ? g_Bb : g_A) + base;
    float2* __restrict__       Y = (inIsB ? g_A : g_Bb) + base;
    int s_ = 1 << log2s;
    int q  = tid & (s_ - 1);
    int p  = tid >> log2s;
    int m  = TN >> (log2s + 4);

    float2 z[16];
#pragma unroll
    for (int j = 0; j < 16; j++) z[j] = X[q + ((p + j * m) << log2s)];
    fft16<FWD>(z);
    float sn, cs;
    sincosf(th0 * (float)p, &sn, &cs);
    float2 w = make_float2(cs, sn), cur = w;
    int ob = q + ((p << 4) << log2s);
    Y[ob] = z[0];
#pragma unroll
    for (int r = 1; r < 16; r++) {
        Y[ob + (r << log2s)] = cmul(z[r], cur);
        cur = cmul(cur, w);
    }
}

// ---------------- u + Hermitian pack + inverse stage 0 (fused, standalone) ----------------
// H_k[t] = (u_k[t] + conj(u_k[(N-t) mod N]))/2 ; batch0 = H0 + i*H1, batch1 = H2.
// Then ifft gives y0 = Re, y1 = Im of batch0; y2 = Re of batch1.
__device__ __forceinline__ void eval_u(float fr, float2 fh, float2 la,
                                       float om0, float om1, float om2,
                                       float2& u0, float2& u1, float2& u2) {
    float d0 = fr - om0; d0 *= d0;
    float d1 = fr - om1; d1 *= d1;
    float d2 = fr - om2; d2 *= d2;
    float g0 = frcp(fmaf(C_ALPHA, (d0 + C_TAU2) + d1, 1.0f));
    float g1 = frcp(fmaf(C_ALPHA, ((d1 + C_TAU2) + d0) + d2, 1.0f));
    float g2 = frcp(fmaf(C_ALPHA, (d2 + C_TAU2) + d1, 1.0f));
    float G  = (g0 + g1) + g2;
    // invert dual ascent: la_entering = (la_new - tau*fh*(G-1)) / (1 - tau*G/2)
    float inv = frcp(1.0f - 0.5f * C_TAU * G);
    float lox = (la.x - C_TAU * fh.x * (G - 1.0f)) * inv;
    float loy = (la.y - C_TAU * fh.y * (G - 1.0f)) * inv;
    float nr = fmaf(-0.5f, lox, fh.x);
    float ni = fmaf(-0.5f, loy, fh.y);
    u0 = make_float2(nr * g0, ni * g0);
    u1 = make_float2(nr * g1, ni * g1);
    u2 = make_float2(nr * g2, ni * g2);
}

__global__ void __launch_bounds__(256) ustage0_kernel() {
    int gid = blockIdx.x * blockDim.x + threadIdx.x;   // 0..65535
    float om0 = g_om[0], om1 = g_om[1], om2 = g_om[2];
    const float FRC = 1.0f / 1048576.0f;
    float frBase = fmaf((float)gid, FRC, -0.5f);
    int gm = (65536 - gid) & 65535;
    float frmBase = fmaf((float)gm, FRC, -0.5f);

    float2 P[16], Q[16];
#pragma unroll
    for (int j = 0; j < 16; j++) {
        int t  = j * 65536 + gid;
        int jm = (gid == 0) ? ((16 - j) & 15) : (15 - j);
        int tm = jm * 65536 + gm;
        float fr  = frBase + (float)j * 0.0625f;
        float frm = frmBase + (float)jm * 0.0625f;
        float2 u0, u1, u2, v0, v1, v2;
        eval_u(fr,  g_Bb[t],  g_lamPrev[t],  om0, om1, om2, u0, u1, u2);
        eval_u(frm, g_Bb[tm], g_lamPrev[tm], om0, om1, om2, v0, v1, v2);
        float h0x = 0.5f * (u0.x + v0.x), h0y = 0.5f * (u0.y - v0.y);
        float h1x = 0.5f * (u1.x + v1.x), h1y = 0.5f * (u1.y - v1.y);
        P[j] = make_float2(h0x - h1y, h0y + h1x);
        Q[j] = make_float2(0.5f * (u2.x + v2.x), 0.5f * (u2.y - v2.y));
    }

    float th0 = (float)(2.0 * PI_D / (double)TN);
    float sn, cs;
    sincosf(th0 * (float)gid, &sn, &cs);
    float2 w = make_float2(cs, sn);
    int ob = gid << 4;

    fft16<false>(P);
    {
        float2 cur = w;
        g_A[ob] = P[0];
#pragma unroll
        for (int r = 1; r < 16; r++) { g_A[ob + r] = cmul(P[r], cur); cur = cmul(cur, w); }
    }
    fft16<false>(Q);
    {
        float2 cur = w;
        g_A[TN + ob] = Q[0];
#pragma unroll
        for (int r = 1; r < 16; r++) { g_A[TN + ob + r] = cmul(Q[r], cur); cur = cmul(cur, w); }
    }
}

// ---------------- final inverse stage fused with real output (reads g_Bb) ----------------
__global__ void __launch_bounds__(256) inv_final_kernel(float* __restrict__ out) {
    int gid = blockIdx.x * blockDim.x + threadIdx.x;   // 0..131071
    int q = gid & 65535;
    int b = gid >> 16;
    const float2* __restrict__ X = g_Bb + (b << LOG2TN);
    float2 z[16];
#pragma unroll
    for (int j = 0; j < 16; j++) z[j] = X[q + (j << 16)];
    fft16<false>(z);
    float sg = (q & 1) ? -(1.0f / 1048576.0f) : (1.0f / 1048576.0f);
    if (b == 0) {
#pragma unroll
        for (int r = 0; r < 16; r++) {
            out[q + (r << 16)]      = z[r].x * sg;   // y0 = Re
            out[TN + q + (r << 16)] = z[r].y * sg;   // y1 = Im
        }
    } else {
#pragma unroll
        for (int r = 0; r < 16; r++)
            out[2 * TN + q + (r << 16)] = z[r].x * sg;  // y2 = Re
    }
}

// ---------------- persistent VMD iteration kernel (packed f32x2, R8 barrier) ----------------
#define NBP 128
#define NTP 512
#define PJ 8      // 8 pairs = 16 elements per thread; NBP*NTP*16 = 2^20

__global__ void __launch_bounds__(NTP) vmd_persist() {
    int tid = threadIdx.x;
    int gid = blockIdx.x * NTP + tid;

    ull fhxP[PJ], fhyP[PJ], laxP[PJ], layP[PJ];
#pragma unroll
    for (int j = 0; j < PJ; j++) {
        float2 v0 = g_Bb[(2 * j) * 65536 + gid];
        float2 v1 = g_Bb[(2 * j + 1) * 65536 + gid];
        fhxP[j] = pk(v0.x, v1.x);
        fhyP[j] = pk(v0.y, v1.y);
        laxP[j] = 0ULL; layP[j] = 0ULL;
    }
    float om0 = g_om[0], om1 = g_om[1], om2 = g_om[2];
    float oD0 = om0, oD1 = om1, oD2 = om2;

    __shared__ float  sred[8][NTP / 32];
    __shared__ double sPrev[8];
    __shared__ float  sOm[3];
    __shared__ int    sTerm;
    if (tid < 8) sPrev[tid] = 0.0;
    __syncthreads();

    const float FRC = 1.0f / 1048576.0f;
    float frBase = fmaf((float)gid, FRC, -0.5f);

    const ull T2P   = pk(C_TAU2, C_TAU2);
    const ull ONEP  = pk(1.0f, 1.0f);
    const ull ALP   = pk(C_ALPHA, C_ALPHA);
    const ull NHALF = pk(-0.5f, -0.5f);
    const ull TAUP  = pk(C_TAU, C_TAU);
    const ull NTAUP = pk(-C_TAU, -C_TAU);
    const ull C1P   = pk(1.0f - 0.5f * C_TAU, 1.0f - 0.5f * C_TAU);

    for (int n = 0; n < 50; n++) {
        ull a0 = 0ULL, a1 = 0ULL, a2 = 0ULL, a3 = 0ULL, a4 = 0ULL, a5 = 0ULL;
        float a6 = 0.f, a7 = 0.f;
        bool doDiff  = (n > 0) && (n % 10 == 0);
        bool doStash = (n % 10 == 9) && (n < 49);

        ull NOM0 = pk(-om0, -om0), NOM1 = pk(-om1, -om1), NOM2 = pk(-om2, -om2);

#pragma unroll
        for (int j = 0; j < PJ; j++) {
            float fr0 = frBase + (float)(2 * j) * 0.0625f;
            float fr1 = fr0 + 0.0625f;
            ull frP = pk(fr0, fr1);

            ull t0 = add2(frP, NOM0); ull d0 = mul2(t0, t0);
            ull t1 = add2(frP, NOM1); ull d1 = mul2(t1, t1);
            ull t2 = add2(frP, NOM2); ull d2 = mul2(t2, t2);
            ull e0 = add2(add2(d0, d1), T2P);
            ull e1 = add2(e0, d2);
            ull e2 = add2(add2(d1, d2), T2P);
            ull g0 = rcp2(fma2(ALP, e0, ONEP));
            ull g1 = rcp2(fma2(ALP, e1, ONEP));
            ull g2 = rcp2(fma2(ALP, e2, ONEP));

            ull nr = fma2(NHALF, laxP[j], fhxP[j]);
            ull ni = fma2(NHALF, layP[j], fhyP[j]);
            ull m2 = fma2(ni, ni, mul2(nr, nr));

            ull p0 = mul2(m2, mul2(g0, g0));
            ull p1 = mul2(m2, mul2(g1, g1));
            ull p2 = mul2(m2, mul2(g2, g2));
            a0 = add2(a0, p0); a1 = add2(a1, p1); a2 = add2(a2, p2);
            a3 = fma2(p0, frP, a3); a4 = fma2(p1, frP, a4); a5 = fma2(p2, frP, a5);

            if (doDiff) {
                float nrl, nrh, nil, nih, g0l, g0h, g1l, g1h, g2l, g2h;
                upk(nrl, nrh, nr); upk(nil, nih, ni);
                upk(g0l, g0h, g0); upk(g1l, g1h, g1); upk(g2l, g2h, g2);
                float fhxl, fhxh, fhyl, fhyh;
                upk(fhxl, fhxh, fhxP[j]); upk(fhyl, fhyh, fhyP[j]);
#pragma unroll
                for (int s = 0; s < 2; s++) {
                    float fr  = s ? fr1 : fr0;
                    float cnr = s ? nrh : nrl, cni = s ? nih : nil;
                    float cg0 = s ? g0h : g0l, cg1 = s ? g1h : g1l, cg2 = s ? g2h : g2l;
                    float cfx = s ? fhxh : fhxl, cfy = s ? fhyh : fhyl;
                    float2 lp = g_lamPrev[(2 * j + s) * 65536 + gid];
                    float q0 = fr - oD0; q0 *= q0;
                    float q1 = fr - oD1; q1 *= q1;
                    float q2 = fr - oD2; q2 *= q2;
                    float h0 = frcp(fmaf(C_ALPHA, (q0 + C_TAU2) + q1, 1.0f));
                    float h1 = frcp(fmaf(C_ALPHA, ((q1 + C_TAU2) + q0) + q2, 1.0f));
                    float h2 = frcp(fmaf(C_ALPHA, (q2 + C_TAU2) + q1, 1.0f));
                    float mr = fmaf(-0.5f, lp.x, cfx);
                    float mi = fmaf(-0.5f, lp.y, cfy);
                    float ex0 = cnr * cg0 - mr * h0, ey0 = cni * cg0 - mi * h0;
                    float ex1 = cnr * cg1 - mr * h1, ey1 = cni * cg1 - mi * h1;
                    float ex2 = cnr * cg2 - mr * h2, ey2 = cni * cg2 - mi * h2;
                    a6 += ex0 * ex0 + ey0 * ey0 + ex1 * ex1 + ey1 * ey1 + ex2 * ex2 + ey2 * ey2;
                    a7 += (mr * mr + mi * mi) * (h0 * h0 + h1 * h1 + h2 * h2);
                }
            }
            if (doStash) {
                float lxl, lxh, lyl, lyh;
                upk(lxl, lxh, laxP[j]); upk(lyl, lyh, layP[j]);
                g_lamPrev[(2 * j) * 65536 + gid]     = make_float2(lxl, lyl);
                g_lamPrev[(2 * j + 1) * 65536 + gid] = make_float2(lxh, lyh);
            }

            ull G   = add2(add2(g0, g1), g2);
            ull tG1 = fma2(TAUP, G, NTAUP);          // tau*(G-1)
            laxP[j] = fma2(nr, tG1, mul2(laxP[j], C1P));
            layP[j] = fma2(ni, tG1, mul2(layP[j], C1P));
        }

        // ---- unpack packed accumulators, block reduce 8 scalars ----
        float vals[8];
        {
            float lo, hi;
            upk(lo, hi, a0); vals[0] = lo + hi;
            upk(lo, hi, a1); vals[1] = lo + hi;
            upk(lo, hi, a2); vals[2] = lo + hi;
            upk(lo, hi, a3); vals[3] = lo + hi;
            upk(lo, hi, a4); vals[4] = lo + hi;
            upk(lo, hi, a5); vals[5] = lo + hi;
            vals[6] = a6; vals[7] = a7;
        }
#pragma unroll
        for (int i = 0; i < 8; i++) {
            float v = vals[i];
#pragma unroll
            for (int o = 16; o > 0; o >>= 1) v += __shfl_down_sync(0xffffffffu, v, o);
            vals[i] = v;
        }
        int wid = tid >> 5, lid = tid & 31;
        if (lid == 0) {
#pragma unroll
            for (int i = 0; i < 8; i++) sred[i][wid] = vals[i];
        }
        __syncthreads();
        if (tid < 8) {
            double s = 0.0;
#pragma unroll
            for (int w = 0; w < NTP / 32; w++) s += (double)sred[tid][w];
            atomicAdd(&g_accB.a[tid], s);
            __threadfence();
        }
        __syncthreads();

        // ---- arrival; last arriver ONLY writes the release word; hybrid spin ----
        if (tid == 0) {
            unsigned old = atomicAdd(&g_ctrB.c, 1u);
            if (old == (unsigned)NBP * (unsigned)(n + 1) - 1u) {
                __threadfence();
                g_goB.g = (unsigned)(n + 1);
            }
            int sp = 0;
            while (g_goB.g < (unsigned)(n + 1)) { if (++sp > 2048) __nanosleep(64); }
            __threadfence();
            // redundant scalar update from monotone totals (parallel across leaders)
            double T[8];
            float it[8];
#pragma unroll
            for (int i = 0; i < 8; i++) {
                T[i]  = *((const volatile double*)&g_accB.a[i]);
                it[i] = (float)(T[i] - sPrev[i]);
                sPrev[i] = T[i];
            }
            float on0 = it[3] / (it[0] + 1e-8f);
            float on1 = it[4] / (it[1] + 1e-8f);
            float on2 = it[5] / (it[2] + 1e-8f);
            float odiff = (fabsf(on0 - on2) + fabsf(on1 - on0) + fabsf(on2 - on1)) * (1.0f / 3.0f);
            float udiff = (n == 0) ? (it[0] + it[1] + it[2]) * 1e8f
                                   : it[6] / (it[7] + 1e-8f);
            int done = (n % 10 == 0) && (udiff < 1e-6f) && (odiff < 1e-6f);
            sOm[0] = on0; sOm[1] = on1; sOm[2] = on2;
            sTerm = (done || n == 49) ? 1 : 0;
        }
        __syncthreads();

        if (sTerm) {
            // terminal: store raw lambda_new; ustage0_kernel does inversion + u + pack + stage 0
#pragma unroll
            for (int j = 0; j < PJ; j++) {
                float lxl, lxh, lyl, lyh;
                upk(lxl, lxh, laxP[j]); upk(lyl, lyh, layP[j]);
                g_lamPrev[(2 * j) * 65536 + gid]     = make_float2(lxl, lyl);
                g_lamPrev[(2 * j + 1) * 65536 + gid] = make_float2(lxh, lyh);
            }
            if (gid == 0) { g_om[0] = om0; g_om[1] = om1; g_om[2] = om2; }
            break;
        }
        oD0 = om0; oD1 = om1; oD2 = om2;
        om0 = sOm[0]; om1 = sOm[1]; om2 = sOm[2];
        __syncthreads();
    }
}

// ---------------- launch ----------------
extern "C" void kernel_launch(void* const* d_in, const int* in_sizes, int n_in,
                              void* d_out, int out_size) {
    const float* x   = (const float*)d_in[0];
    const float* om0 = (const float*)d_in[1];
    float* out = (float*)d_out;

    // forward FFT of (-1)^n x (stage 0 carries global init)
    fwd0_kernel<<<256, 256>>>(x, om0);
    for (int i = 1; i < 5; i++) {
        float th0 = (float)(-2.0 * PI_D * (double)(1 << (4 * i)) / (double)TN);
        fft16_stage<true><<<256, 256>>>(i & 1, 4 * i, th0);
    }

    vmd_persist<<<NBP, NTP>>>();      // ends by storing final lambda + omega

    ustage0_kernel<<<256, 256>>>();   // lambda -> u -> Hermitian pack (2 batches) + stage 0 -> g_A

    // inverse stages 1..3 (2 batches): A->B->A->B
    for (int i = 1; i < 4; i++) {
        float th0 = (float)(2.0 * PI_D * (double)(1 << (4 * i)) / (double)TN);
        fft16_stage<false><<<512, 256>>>(1 - (i & 1), 4 * i, th0);
    }
    // final stage fused with real output: batch0 -> y0 (Re), y1 (Im); batch1 -> y2 (Re)
    inv_final_kernel<<<512, 256>>>(out);
}